// round 10
// baseline (speedup 1.0000x reference)
#include <cuda_runtime.h>
#include <stdint.h>

// ---------------------------------------------------------------------------
// PairLoss: result = ( sum_{gt<0.5} exp(p) * sum_{gt>0.5} exp(-p) - n_neg ) / 2
//
// Streaming reduction over 2 x 128MB fp32. Measured: LDG.128, LDG.128 x2,
// and deep cp.async pipelines ALL pin at 5.6-5.9 TB/s with DRAM ~70% busy and
// no pipe saturated -> in-flight bytes are not the limiter; testing request
// WIDTH: sm_100a 256-bit loads (ld.global.nc.v8.f32, LDG.E.256) halve the
// wavefront count per byte.
//
// Deterministic (fixed-order fp64 final combine in last-arriving block),
// graph-capturable, allocation-free.
// ---------------------------------------------------------------------------

#define NBLOCKS 1184
#define NTHREADS 256

__device__ double g_part[3 * NBLOCKS];
__device__ unsigned int g_done = 0;   // self-resetting arrival counter

// 256-bit global load: 8 floats per instruction (sm_100a LDG.E.256).
__device__ __forceinline__ void ldg256(const float* p, float4& a, float4& b) {
    asm volatile(
        "ld.global.nc.v8.f32 {%0,%1,%2,%3,%4,%5,%6,%7}, [%8];"
        : "=f"(a.x), "=f"(a.y), "=f"(a.z), "=f"(a.w),
          "=f"(b.x), "=f"(b.y), "=f"(b.z), "=f"(b.w)
        : "l"(p));
}

__device__ __forceinline__ void accum_one(float p, float g, float& s_neg,
                                          float& s_pos, float& cnt) {
    bool pos = g > 0.5f;
    float e = __expf(pos ? -p : p);
    if (pos) s_pos += e;
    else { s_neg += e; cnt += 1.0f; }
}

__device__ __forceinline__ void accum4(const float4& p, const float4& g,
                                       float& s_neg, float& s_pos, float& cnt) {
    accum_one(p.x, g.x, s_neg, s_pos, cnt);
    accum_one(p.y, g.y, s_neg, s_pos, cnt);
    accum_one(p.z, g.z, s_neg, s_pos, cnt);
    accum_one(p.w, g.w, s_neg, s_pos, cnt);
}

// Reduce three values across the block; results valid on (warp 0, lane 0).
template <typename T>
__device__ __forceinline__ void block_reduce3(T& a, T& b, T& c, T* sh) {
    int lane = threadIdx.x & 31;
    int warp = threadIdx.x >> 5;
    const int nw = NTHREADS / 32;

    #pragma unroll
    for (int off = 16; off > 0; off >>= 1) {
        a += __shfl_down_sync(0xffffffffu, a, off);
        b += __shfl_down_sync(0xffffffffu, b, off);
        c += __shfl_down_sync(0xffffffffu, c, off);
    }
    if (lane == 0) { sh[warp] = a; sh[nw + warp] = b; sh[2 * nw + warp] = c; }
    __syncthreads();
    if (warp == 0) {
        a = (lane < nw) ? sh[lane] : (T)0;
        b = (lane < nw) ? sh[nw + lane] : (T)0;
        c = (lane < nw) ? sh[2 * nw + lane] : (T)0;
        #pragma unroll
        for (int off = 16; off > 0; off >>= 1) {
            a += __shfl_down_sync(0xffffffffu, a, off);
            b += __shfl_down_sync(0xffffffffu, b, off);
            c += __shfl_down_sync(0xffffffffu, c, off);
        }
    }
}

__device__ __forceinline__ void epilogue(float s_neg, float s_pos, float cnt,
                                         float* __restrict__ out) {
    __shared__ float shf[3 * (NTHREADS / 32)];
    block_reduce3(s_neg, s_pos, cnt, shf);

    __shared__ bool s_last;
    if (threadIdx.x == 0) {
        g_part[blockIdx.x]               = (double)s_neg;
        g_part[NBLOCKS + blockIdx.x]     = (double)s_pos;
        g_part[2 * NBLOCKS + blockIdx.x] = (double)cnt;
        __threadfence();
        unsigned int prev = atomicAdd(&g_done, 1u);
        s_last = (prev == (unsigned int)(gridDim.x - 1));
    }
    __syncthreads();

    if (s_last) {
        __threadfence();  // acquire: all blocks' partials now visible
        double a = 0.0, b = 0.0, c = 0.0;
        for (int k = threadIdx.x; k < NBLOCKS; k += NTHREADS) {
            a += g_part[k];
            b += g_part[NBLOCKS + k];
            c += g_part[2 * NBLOCKS + k];
        }
        __shared__ double shd[3 * (NTHREADS / 32)];
        block_reduce3(a, b, c, shd);
        if (threadIdx.x == 0) {
            out[0] = (float)((a * b - c) * 0.5);
            g_done = 0;  // reset for next graph replay
        }
    }
}

__global__ void __launch_bounds__(NTHREADS)
pairloss_v8(const float* __restrict__ pred, const float* __restrict__ gt,
            int n, float* __restrict__ out) {
    float s_neg = 0.0f, s_pos = 0.0f, cnt = 0.0f;
    const int n8 = n >> 3;                // number of 8-float chunks
    const int stride = gridDim.x * blockDim.x;

    // x1 grid-stride, 2 x LDG.E.256 per iteration (front-batch = 2 instrs).
    for (int i = blockIdx.x * blockDim.x + threadIdx.x; i < n8; i += stride) {
        float4 p0, p1, g0, g1;
        ldg256(pred + ((size_t)i << 3), p0, p1);
        ldg256(gt   + ((size_t)i << 3), g0, g1);
        accum4(p0, g0, s_neg, s_pos, cnt);
        accum4(p1, g1, s_neg, s_pos, cnt);
    }
    // scalar tail (n % 8)
    for (int t = (n8 << 3) + blockIdx.x * blockDim.x + threadIdx.x; t < n;
         t += stride) {
        accum_one(pred[t], gt[t], s_neg, s_pos, cnt);
    }

    epilogue(s_neg, s_pos, cnt, out);
}

// Scalar fallback for insufficiently aligned inputs (not expected).
__global__ void __launch_bounds__(NTHREADS)
pairloss_scalar(const float* __restrict__ pred, const float* __restrict__ gt,
                int n, float* __restrict__ out) {
    float s_neg = 0.0f, s_pos = 0.0f, cnt = 0.0f;
    int stride = gridDim.x * blockDim.x;
    for (int i = blockIdx.x * blockDim.x + threadIdx.x; i < n; i += stride)
        accum_one(pred[i], gt[i], s_neg, s_pos, cnt);
    epilogue(s_neg, s_pos, cnt, out);
}

extern "C" void kernel_launch(void* const* d_in, const int* in_sizes, int n_in,
                              void* d_out, int out_size) {
    const float* pred = (const float*)d_in[0];
    const float* gt   = (const float*)d_in[1];
    float* out = (float*)d_out;
    int n = in_sizes[0];

    // v8 path needs 32B alignment.
    bool aligned = (((uintptr_t)pred | (uintptr_t)gt) & 0x1F) == 0;
    if (aligned) {
        pairloss_v8<<<NBLOCKS, NTHREADS>>>(pred, gt, n, out);
    } else {
        pairloss_scalar<<<NBLOCKS, NTHREADS>>>(pred, gt, n, out);
    }
}

// round 12
// speedup vs baseline: 1.0415x; 1.0415x over previous
#include <cuda_runtime.h>
#include <stdint.h>

// ---------------------------------------------------------------------------
// PairLoss: result = ( sum_{gt<0.5} exp(p) * sum_{gt>0.5} exp(-p) - n_neg ) / 2
//
// Streaming reduction over 2 x 128MB fp32. Empirical finding (R5/R6/R9/R10):
// LDG.128, LDG.128x2, cp.async pipeline, and LDG.E.256 all pin at
// 5.6-5.9 TB/s with DRAM ~70% busy and nothing else saturated -> SM<->L2
// fabric ceiling, invariant to request generation. So: simplest load path
// (__ldcs float4, x1 grid-stride = best measured), and minimize the
// non-overlapped overheads: 592x512 config halves the partial count and the
// last-block final-combine latency.
//
// Deterministic (fixed-order fp64 final combine in last-arriving block),
// graph-capturable, allocation-free.
// ---------------------------------------------------------------------------

#define NBLOCKS 592
#define NTHREADS 512

__device__ double g_part[3 * NBLOCKS];
__device__ unsigned int g_done = 0;   // self-resetting arrival counter

__device__ __forceinline__ void accum_one(float p, float g, float& s_neg,
                                          float& s_pos, float& cnt) {
    bool pos = g > 0.5f;
    float e = __expf(pos ? -p : p);
    if (pos) s_pos += e;
    else { s_neg += e; cnt += 1.0f; }
}

// Reduce three values across the block; results valid on (warp 0, lane 0).
template <typename T>
__device__ __forceinline__ void block_reduce3(T& a, T& b, T& c, T* sh) {
    int lane = threadIdx.x & 31;
    int warp = threadIdx.x >> 5;
    const int nw = NTHREADS / 32;

    #pragma unroll
    for (int off = 16; off > 0; off >>= 1) {
        a += __shfl_down_sync(0xffffffffu, a, off);
        b += __shfl_down_sync(0xffffffffu, b, off);
        c += __shfl_down_sync(0xffffffffu, c, off);
    }
    if (lane == 0) { sh[warp] = a; sh[nw + warp] = b; sh[2 * nw + warp] = c; }
    __syncthreads();
    if (warp == 0) {
        a = (lane < nw) ? sh[lane] : (T)0;
        b = (lane < nw) ? sh[nw + lane] : (T)0;
        c = (lane < nw) ? sh[2 * nw + lane] : (T)0;
        #pragma unroll
        for (int off = 16; off > 0; off >>= 1) {
            a += __shfl_down_sync(0xffffffffu, a, off);
            b += __shfl_down_sync(0xffffffffu, b, off);
            c += __shfl_down_sync(0xffffffffu, c, off);
        }
    }
}

__device__ __forceinline__ void epilogue(float s_neg, float s_pos, float cnt,
                                         float* __restrict__ out) {
    __shared__ float shf[3 * (NTHREADS / 32)];
    block_reduce3(s_neg, s_pos, cnt, shf);

    __shared__ bool s_last;
    if (threadIdx.x == 0) {
        g_part[blockIdx.x]               = (double)s_neg;
        g_part[NBLOCKS + blockIdx.x]     = (double)s_pos;
        g_part[2 * NBLOCKS + blockIdx.x] = (double)cnt;
        __threadfence();
        unsigned int prev = atomicAdd(&g_done, 1u);
        s_last = (prev == (unsigned int)(gridDim.x - 1));
    }
    __syncthreads();

    if (s_last) {
        __threadfence();  // acquire: all blocks' partials now visible
        // 592 partials x3: each thread reads <=2 per array; L2-hot.
        double a = 0.0, b = 0.0, c = 0.0;
        for (int k = threadIdx.x; k < NBLOCKS; k += NTHREADS) {
            a += g_part[k];
            b += g_part[NBLOCKS + k];
            c += g_part[2 * NBLOCKS + k];
        }
        __shared__ double shd[3 * (NTHREADS / 32)];
        block_reduce3(a, b, c, shd);
        if (threadIdx.x == 0) {
            out[0] = (float)((a * b - c) * 0.5);
            g_done = 0;  // reset for next graph replay
        }
    }
}

__global__ void __launch_bounds__(NTHREADS)
pairloss_stream(const float4* __restrict__ p4, const float4* __restrict__ g4,
                const float* __restrict__ pred, const float* __restrict__ gt,
                int n, float* __restrict__ out) {
    float s_neg = 0.0f, s_pos = 0.0f, cnt = 0.0f;
    const int n4 = n >> 2;
    const int stride = gridDim.x * blockDim.x;

    // x1 grid-stride, streaming loads (evict-first; one-touch data).
    for (int i = blockIdx.x * blockDim.x + threadIdx.x; i < n4; i += stride) {
        float4 p = __ldcs(p4 + i);
        float4 g = __ldcs(g4 + i);
        accum_one(p.x, g.x, s_neg, s_pos, cnt);
        accum_one(p.y, g.y, s_neg, s_pos, cnt);
        accum_one(p.z, g.z, s_neg, s_pos, cnt);
        accum_one(p.w, g.w, s_neg, s_pos, cnt);
    }
    // scalar tail (n % 4)
    for (int t = (n4 << 2) + blockIdx.x * blockDim.x + threadIdx.x; t < n;
         t += stride) {
        accum_one(__ldcs(pred + t), __ldcs(gt + t), s_neg, s_pos, cnt);
    }

    epilogue(s_neg, s_pos, cnt, out);
}

// Scalar fallback for unaligned inputs (not expected from the harness).
__global__ void __launch_bounds__(NTHREADS)
pairloss_scalar(const float* __restrict__ pred, const float* __restrict__ gt,
                int n, float* __restrict__ out) {
    float s_neg = 0.0f, s_pos = 0.0f, cnt = 0.0f;
    int stride = gridDim.x * blockDim.x;
    for (int i = blockIdx.x * blockDim.x + threadIdx.x; i < n; i += stride)
        accum_one(pred[i], gt[i], s_neg, s_pos, cnt);
    epilogue(s_neg, s_pos, cnt, out);
}

extern "C" void kernel_launch(void* const* d_in, const int* in_sizes, int n_in,
                              void* d_out, int out_size) {
    const float* pred = (const float*)d_in[0];
    const float* gt   = (const float*)d_in[1];
    float* out = (float*)d_out;
    int n = in_sizes[0];

    bool aligned = (((uintptr_t)pred | (uintptr_t)gt) & 0xF) == 0;
    if (aligned) {
        pairloss_stream<<<NBLOCKS, NTHREADS>>>(
            (const float4*)pred, (const float4*)gt, pred, gt, n, out);
    } else {
        pairloss_scalar<<<NBLOCKS, NTHREADS>>>(pred, gt, n, out);
    }
}

// round 13
// speedup vs baseline: 1.0438x; 1.0021x over previous
#include <cuda_runtime.h>
#include <stdint.h>

// ---------------------------------------------------------------------------
// PairLoss: result = ( sum_{gt<0.5} exp(p) * sum_{gt>0.5} exp(-p) - n_neg ) / 2
//
// Streaming reduction over 2 x 128MB fp32. Plateau characterized across
// LDG.128 / LDG.128x2 / cp.async / LDG.E.256: ~5.6-6.0 TB/s effective read
// ceiling (DRAM ~73%, nothing else saturated). Best measured: __ldcs float4
// x1 grid-stride. Only remaining lever is concurrency shape + epilogue
// overhead: 296 blocks x 1024 threads (2 CTA/SM, one exact wave) halves the
// partial count again (296) and the arrival/combine cost.
//
// Deterministic (fixed-order fp64 final combine in last-arriving block),
// graph-capturable, allocation-free.
// ---------------------------------------------------------------------------

#define NBLOCKS 296
#define NTHREADS 1024

__device__ double g_part[3 * NBLOCKS];
__device__ unsigned int g_done = 0;   // self-resetting arrival counter

__device__ __forceinline__ void accum_one(float p, float g, float& s_neg,
                                          float& s_pos, float& cnt) {
    bool pos = g > 0.5f;
    float e = __expf(pos ? -p : p);
    if (pos) s_pos += e;
    else { s_neg += e; cnt += 1.0f; }
}

// Reduce three values across the block; results valid on (warp 0, lane 0).
template <typename T>
__device__ __forceinline__ void block_reduce3(T& a, T& b, T& c, T* sh) {
    int lane = threadIdx.x & 31;
    int warp = threadIdx.x >> 5;
    const int nw = NTHREADS / 32;

    #pragma unroll
    for (int off = 16; off > 0; off >>= 1) {
        a += __shfl_down_sync(0xffffffffu, a, off);
        b += __shfl_down_sync(0xffffffffu, b, off);
        c += __shfl_down_sync(0xffffffffu, c, off);
    }
    if (lane == 0) { sh[warp] = a; sh[nw + warp] = b; sh[2 * nw + warp] = c; }
    __syncthreads();
    if (warp == 0) {
        a = (lane < nw) ? sh[lane] : (T)0;
        b = (lane < nw) ? sh[nw + lane] : (T)0;
        c = (lane < nw) ? sh[2 * nw + lane] : (T)0;
        #pragma unroll
        for (int off = 16; off > 0; off >>= 1) {
            a += __shfl_down_sync(0xffffffffu, a, off);
            b += __shfl_down_sync(0xffffffffu, b, off);
            c += __shfl_down_sync(0xffffffffu, c, off);
        }
    }
}

__device__ __forceinline__ void epilogue(float s_neg, float s_pos, float cnt,
                                         float* __restrict__ out) {
    __shared__ float shf[3 * (NTHREADS / 32)];
    block_reduce3(s_neg, s_pos, cnt, shf);

    __shared__ bool s_last;
    if (threadIdx.x == 0) {
        g_part[blockIdx.x]               = (double)s_neg;
        g_part[NBLOCKS + blockIdx.x]     = (double)s_pos;
        g_part[2 * NBLOCKS + blockIdx.x] = (double)cnt;
        __threadfence();
        unsigned int prev = atomicAdd(&g_done, 1u);
        s_last = (prev == (unsigned int)(gridDim.x - 1));
    }
    __syncthreads();

    if (s_last) {
        __threadfence();  // acquire: all blocks' partials now visible
        // 296 partials x3: single strided read per thread; L2-hot.
        double a = 0.0, b = 0.0, c = 0.0;
        for (int k = threadIdx.x; k < NBLOCKS; k += NTHREADS) {
            a += g_part[k];
            b += g_part[NBLOCKS + k];
            c += g_part[2 * NBLOCKS + k];
        }
        __shared__ double shd[3 * (NTHREADS / 32)];
        block_reduce3(a, b, c, shd);
        if (threadIdx.x == 0) {
            out[0] = (float)((a * b - c) * 0.5);
            g_done = 0;  // reset for next graph replay
        }
    }
}

__global__ void __launch_bounds__(NTHREADS)
pairloss_stream(const float4* __restrict__ p4, const float4* __restrict__ g4,
                const float* __restrict__ pred, const float* __restrict__ gt,
                int n, float* __restrict__ out) {
    float s_neg = 0.0f, s_pos = 0.0f, cnt = 0.0f;
    const int n4 = n >> 2;
    const int stride = gridDim.x * blockDim.x;

    // x1 grid-stride, streaming loads (evict-first; one-touch data).
    for (int i = blockIdx.x * blockDim.x + threadIdx.x; i < n4; i += stride) {
        float4 p = __ldcs(p4 + i);
        float4 g = __ldcs(g4 + i);
        accum_one(p.x, g.x, s_neg, s_pos, cnt);
        accum_one(p.y, g.y, s_neg, s_pos, cnt);
        accum_one(p.z, g.z, s_neg, s_pos, cnt);
        accum_one(p.w, g.w, s_neg, s_pos, cnt);
    }
    // scalar tail (n % 4)
    for (int t = (n4 << 2) + blockIdx.x * blockDim.x + threadIdx.x; t < n;
         t += stride) {
        accum_one(__ldcs(pred + t), __ldcs(gt + t), s_neg, s_pos, cnt);
    }

    epilogue(s_neg, s_pos, cnt, out);
}

// Scalar fallback for unaligned inputs (not expected from the harness).
__global__ void __launch_bounds__(NTHREADS)
pairloss_scalar(const float* __restrict__ pred, const float* __restrict__ gt,
                int n, float* __restrict__ out) {
    float s_neg = 0.0f, s_pos = 0.0f, cnt = 0.0f;
    int stride = gridDim.x * blockDim.x;
    for (int i = blockIdx.x * blockDim.x + threadIdx.x; i < n; i += stride)
        accum_one(pred[i], gt[i], s_neg, s_pos, cnt);
    epilogue(s_neg, s_pos, cnt, out);
}

extern "C" void kernel_launch(void* const* d_in, const int* in_sizes, int n_in,
                              void* d_out, int out_size) {
    const float* pred = (const float*)d_in[0];
    const float* gt   = (const float*)d_in[1];
    float* out = (float*)d_out;
    int n = in_sizes[0];

    bool aligned = (((uintptr_t)pred | (uintptr_t)gt) & 0xF) == 0;
    if (aligned) {
        pairloss_stream<<<NBLOCKS, NTHREADS>>>(
            (const float4*)pred, (const float4*)gt, pred, gt, n, out);
    } else {
        pairloss_scalar<<<NBLOCKS, NTHREADS>>>(pred, gt, n, out);
    }
}